// round 1
// baseline (speedup 1.0000x reference)
#include <cuda_runtime.h>
#include <cstdint>

#define S_LEN   2048
#define DMODEL  2048
#define NHEADS  16
#define DHEAD   128
#define BATCH   2
#define MTOT    (BATCH * S_LEN)        // 4096 rows for the GEMMs

// Scratch (static device globals — no runtime allocation)
__device__ float g_qkv[BATCH * S_LEN * 3 * DMODEL];   // [B,S,6144]  ~100 MB
__device__ float g_att[BATCH * S_LEN * DMODEL];       // [B,S,2048]  ~33 MB

// ---------------------------------------------------------------------------
// SGEMM: C[M,N] = A[M,K] @ B[K,N] + bias[N]
// 128x128 block tile, K-tile 8, 256 threads, 8x8 micro-tile per thread.
// ---------------------------------------------------------------------------
__global__ __launch_bounds__(256) void sgemm_bias_kernel(
    const float* __restrict__ A, const float* __restrict__ Bm,
    const float* __restrict__ bias, float* __restrict__ C,
    int M, int N, int K)
{
    __shared__ float As[8][128];   // [k][m] (A stored transposed)
    __shared__ float Bs[8][128];   // [k][n]

    int tid = threadIdx.x;
    int tx = tid & 15, ty = tid >> 4;
    int bm = blockIdx.y * 128, bn = blockIdx.x * 128;

    // Global-load assignments
    int a_r = tid >> 1, a_c = (tid & 1) * 4;         // 128 rows x 8 k, float4
    int b_r = tid >> 5, b_c = (tid & 31) * 4;        // 8 k x 128 cols, float4

    const float* Ap = A + (size_t)(bm + a_r) * K + a_c;
    const float* Bp = Bm + (size_t)b_r * N + bn + b_c;

    float acc[8][8];
#pragma unroll
    for (int i = 0; i < 8; i++)
#pragma unroll
        for (int j = 0; j < 8; j++) acc[i][j] = 0.f;

    for (int k0 = 0; k0 < K; k0 += 8) {
        float4 av = *(const float4*)(Ap + k0);
        float4 bv = *(const float4*)(Bp + (size_t)k0 * N);
        __syncthreads();
        As[a_c + 0][a_r] = av.x; As[a_c + 1][a_r] = av.y;
        As[a_c + 2][a_r] = av.z; As[a_c + 3][a_r] = av.w;
        *(float4*)&Bs[b_r][b_c] = bv;
        __syncthreads();
#pragma unroll
        for (int kk = 0; kk < 8; kk++) {
            float a[8], bb[8];
#pragma unroll
            for (int i = 0; i < 8; i++) a[i] = As[kk][ty * 8 + i];
#pragma unroll
            for (int j = 0; j < 8; j++) bb[j] = Bs[kk][tx * 8 + j];
#pragma unroll
            for (int i = 0; i < 8; i++)
#pragma unroll
                for (int j = 0; j < 8; j++) acc[i][j] += a[i] * bb[j];
        }
    }

#pragma unroll
    for (int i = 0; i < 8; i++) {
        size_t row = (size_t)(bm + ty * 8 + i);
        float* cp = C + row * N + bn + tx * 8;
#pragma unroll
        for (int j = 0; j < 8; j++) cp[j] = acc[i][j] + bias[bn + tx * 8 + j];
    }
}

// ---------------------------------------------------------------------------
// Flash attention (causal), fp32.
// Grid: (S/64, NHEADS, BATCH). Block: 256 threads.
// Q tile 64x128 in smem, loop over K/V tiles of 64 keys.
// Thread grid 16x16: scores 4x4 per thread; O 4 rows x 8 cols per thread.
// ---------------------------------------------------------------------------
#define TQ 64
#define TK 64
#define QK_STR 132            // 128 + 4 pad (bank-conflict break, keeps float4 align)
#define P_STR  68

#define ATTN_SMEM_FLOATS (3 * TQ * QK_STR + TQ * P_STR + 3 * TQ)
#define ATTN_SMEM_BYTES  (ATTN_SMEM_FLOATS * 4)      // 119552 bytes

__global__ __launch_bounds__(256) void attn_kernel()
{
    extern __shared__ float sm[];
    float* Qs   = sm;                       // 64*132
    float* Ks   = Qs + TQ * QK_STR;         // 64*132
    float* Vs   = Ks + TK * QK_STR;         // 64*132
    float* Ps   = Vs + TK * QK_STR;         // 64*68
    float* m_sm = Ps + TQ * P_STR;          // 64
    float* l_sm = m_sm + TQ;                // 64
    float* a_sm = l_sm + TQ;                // 64

    int tid = threadIdx.x;
    int tx = tid & 15, ty = tid >> 4;
    int qt = blockIdx.x, h = blockIdx.y, b = blockIdx.z;
    int q0 = qt * TQ;

    const float* base  = g_qkv + (size_t)b * S_LEN * (3 * DMODEL);
    const float* qbase = base + h * DHEAD;
    const float* kbase = base + DMODEL + h * DHEAD;
    const float* vbase = base + 2 * DMODEL + h * DHEAD;

    // Load Q tile (64 x 128), float4 from gmem, scalars into padded smem
    for (int idx = tid; idx < TQ * (DHEAD / 4); idx += 256) {
        int r = idx >> 5;
        int c = (idx & 31) * 4;
        float4 v = *(const float4*)(qbase + (size_t)(q0 + r) * (3 * DMODEL) + c);
        float* dst = Qs + r * QK_STR + c;
        dst[0] = v.x; dst[1] = v.y; dst[2] = v.z; dst[3] = v.w;
    }
    if (tid < TQ) { m_sm[tid] = -1e30f; l_sm[tid] = 0.f; }

    float o[4][8];
#pragma unroll
    for (int i = 0; i < 4; i++)
#pragma unroll
        for (int j = 0; j < 8; j++) o[i][j] = 0.f;

    const float scale = 0.08838834764831845f;  // 1/sqrt(128)

    for (int kt = 0; kt <= qt; kt++) {
        __syncthreads();   // prev iter done with Ks/Vs/Ps; Q load visible on first iter

        // Load K and V tiles
        for (int idx = tid; idx < TK * (DHEAD / 4); idx += 256) {
            int r = idx >> 5;
            int c = (idx & 31) * 4;
            size_t g = (size_t)(kt * TK + r) * (3 * DMODEL) + c;
            float4 kv = *(const float4*)(kbase + g);
            float4 vv = *(const float4*)(vbase + g);
            float* kd = Ks + r * QK_STR + c;
            kd[0] = kv.x; kd[1] = kv.y; kd[2] = kv.z; kd[3] = kv.w;
            float* vd = Vs + r * QK_STR + c;
            vd[0] = vv.x; vd[1] = vv.y; vd[2] = vv.z; vd[3] = vv.w;
        }
        __syncthreads();

        // Scores S = Q K^T (4x4 per thread)
        float s[4][4];
#pragma unroll
        for (int i = 0; i < 4; i++)
#pragma unroll
            for (int j = 0; j < 4; j++) s[i][j] = 0.f;

        for (int d = 0; d < DHEAD; d++) {
            float a[4], bb[4];
#pragma unroll
            for (int i = 0; i < 4; i++) a[i] = Qs[(ty * 4 + i) * QK_STR + d];
#pragma unroll
            for (int j = 0; j < 4; j++) bb[j] = Ks[(tx * 4 + j) * QK_STR + d];
#pragma unroll
            for (int i = 0; i < 4; i++)
#pragma unroll
                for (int j = 0; j < 4; j++) s[i][j] += a[i] * bb[j];
        }

        // Scale + causal mask
#pragma unroll
        for (int i = 0; i < 4; i++) {
            int qg = q0 + ty * 4 + i;
#pragma unroll
            for (int j = 0; j < 4; j++) {
                int kg = kt * TK + tx * 4 + j;
                s[i][j] = (kg <= qg) ? s[i][j] * scale : -1e30f;
            }
        }

        // Row max across the 16-thread tx-group (16 lanes of one half-warp)
        float rmax[4];
#pragma unroll
        for (int i = 0; i < 4; i++) {
            float v = fmaxf(fmaxf(s[i][0], s[i][1]), fmaxf(s[i][2], s[i][3]));
#pragma unroll
            for (int off = 1; off < 16; off <<= 1)
                v = fmaxf(v, __shfl_xor_sync(0xffffffffu, v, off));
            rmax[i] = v;
        }
        if (tx == 0) {
#pragma unroll
            for (int i = 0; i < 4; i++) {
                int r = ty * 4 + i;
                float mo = m_sm[r];
                float mn = fmaxf(mo, rmax[i]);
                a_sm[r] = __expf(mo - mn);
                m_sm[r] = mn;
            }
        }
        __syncthreads();  // m_sm / a_sm visible

        // p = exp(s - m), write to Ps, accumulate row sums
        float rs[4];
#pragma unroll
        for (int i = 0; i < 4; i++) {
            int r = ty * 4 + i;
            float mn = m_sm[r];
            float su = 0.f;
#pragma unroll
            for (int j = 0; j < 4; j++) {
                float p = __expf(s[i][j] - mn);
                Ps[r * P_STR + tx * 4 + j] = p;
                su += p;
            }
            rs[i] = su;
        }
#pragma unroll
        for (int i = 0; i < 4; i++)
#pragma unroll
            for (int off = 1; off < 16; off <<= 1)
                rs[i] += __shfl_xor_sync(0xffffffffu, rs[i], off);
        if (tx == 0) {
#pragma unroll
            for (int i = 0; i < 4; i++) {
                int r = ty * 4 + i;
                l_sm[r] = l_sm[r] * a_sm[r] + rs[i];
            }
        }

        // Rescale running O by alpha
#pragma unroll
        for (int i = 0; i < 4; i++) {
            float al = a_sm[ty * 4 + i];
#pragma unroll
            for (int j = 0; j < 8; j++) o[i][j] *= al;
        }
        __syncthreads();  // Ps fully written

        // O += P @ V   (rows ty*4.., cols tx*8..)
        for (int kk = 0; kk < TK; kk++) {
            float a[4], v[8];
#pragma unroll
            for (int i = 0; i < 4; i++) a[i] = Ps[(ty * 4 + i) * P_STR + kk];
#pragma unroll
            for (int j = 0; j < 8; j++) v[j] = Vs[kk * QK_STR + tx * 8 + j];
#pragma unroll
            for (int i = 0; i < 4; i++)
#pragma unroll
                for (int j = 0; j < 8; j++) o[i][j] += a[i] * v[j];
        }
    }

    __syncthreads();  // final l_sm visible
#pragma unroll
    for (int i = 0; i < 4; i++) {
        int r = ty * 4 + i;
        float inv = 1.0f / l_sm[r];
        float* op = g_att + ((size_t)b * S_LEN + q0 + r) * DMODEL + h * DHEAD + tx * 8;
#pragma unroll
        for (int j = 0; j < 8; j++) op[j] = o[i][j] * inv;
    }
}

// ---------------------------------------------------------------------------
extern "C" void kernel_launch(void* const* d_in, const int* in_sizes, int n_in,
                              void* d_out, int out_size)
{
    const float* x     = (const float*)d_in[0];
    const float* W_qkv = (const float*)d_in[1];
    const float* b_qkv = (const float*)d_in[2];
    const float* W_out = (const float*)d_in[3];
    const float* b_out = (const float*)d_in[4];
    float* out = (float*)d_out;

    float *qkv = nullptr, *att = nullptr;
    cudaGetSymbolAddress((void**)&qkv, g_qkv);
    cudaGetSymbolAddress((void**)&att, g_att);

    cudaFuncSetAttribute(attn_kernel,
                         cudaFuncAttributeMaxDynamicSharedMemorySize,
                         ATTN_SMEM_BYTES);

    // 1) qkv = x @ W_qkv + b_qkv     [4096 x 6144], K=2048
    sgemm_bias_kernel<<<dim3(3 * DMODEL / 128, MTOT / 128), 256>>>(
        x, W_qkv, b_qkv, qkv, MTOT, 3 * DMODEL, DMODEL);

    // 2) causal flash attention -> g_att  [B,S,DMODEL]
    attn_kernel<<<dim3(S_LEN / TQ, NHEADS, BATCH), 256, ATTN_SMEM_BYTES>>>();

    // 3) out = att @ W_out + b_out   [4096 x 2048], K=2048
    sgemm_bias_kernel<<<dim3(DMODEL / 128, MTOT / 128), 256>>>(
        att, W_out, b_out, out, MTOT, DMODEL, DMODEL);
}

// round 2
// speedup vs baseline: 1.4973x; 1.4973x over previous
#include <cuda_runtime.h>
#include <cuda_bf16.h>
#include <cstdint>

#define S_LEN   2048
#define DMODEL  2048
#define NHEADS  16
#define DHEAD   128
#define BATCH   2
#define MTOT    (BATCH * S_LEN)        // 4096 rows for the GEMMs

// Scratch (static device globals — no runtime allocation)
__device__ float g_qkv[BATCH * S_LEN * 3 * DMODEL];   // [B,S,6144]
__device__ float g_att[BATCH * S_LEN * DMODEL];       // [B,S,2048]

// ===========================================================================
// bf16x3 tensor-core GEMM:  C[M,N] = A[M,K] @ B[K,N] + bias[N]
// A,B fp32 in global; split on the fly into bf16 hi/lo in smem.
// C ~= Ahi*Bhi + Ahi*Blo + Alo*Bhi  (fp32 accumulate, ~1e-5 rel err)
// Block tile 128x128, k-tile 32. 256 threads = 8 warps (4x2), warp tile 32x64.
// ===========================================================================
#define BM 128
#define BN 128
#define BK 32
#define ASTR 40    // bf16 row stride for A tiles: 80B = odd multiple of 16B -> conflict-free ldmatrix
#define BSTR 136   // bf16 row stride for B tiles: 272B = odd multiple of 16B

__device__ __forceinline__ void split2(float a, float b, uint32_t& hi, uint32_t& lo) {
    __nv_bfloat162 h = __floats2bfloat162_rn(a, b);
    float la = a - __bfloat162float(h.x);
    float lb = b - __bfloat162float(h.y);
    __nv_bfloat162 l = __floats2bfloat162_rn(la, lb);
    hi = *reinterpret_cast<uint32_t*>(&h);
    lo = *reinterpret_cast<uint32_t*>(&l);
}

__device__ __forceinline__ void ldm_x4(uint32_t* r, const void* p) {
    uint32_t a = (uint32_t)__cvta_generic_to_shared(p);
    asm volatile("ldmatrix.sync.aligned.m8n8.x4.shared.b16 {%0,%1,%2,%3}, [%4];"
                 : "=r"(r[0]), "=r"(r[1]), "=r"(r[2]), "=r"(r[3]) : "r"(a));
}
__device__ __forceinline__ void ldm_x4_t(uint32_t* r, const void* p) {
    uint32_t a = (uint32_t)__cvta_generic_to_shared(p);
    asm volatile("ldmatrix.sync.aligned.m8n8.x4.trans.shared.b16 {%0,%1,%2,%3}, [%4];"
                 : "=r"(r[0]), "=r"(r[1]), "=r"(r[2]), "=r"(r[3]) : "r"(a));
}
__device__ __forceinline__ void mma_bf16(float* c, const uint32_t* a, uint32_t b0, uint32_t b1) {
    asm volatile(
        "mma.sync.aligned.m16n8k16.row.col.f32.bf16.bf16.f32 "
        "{%0,%1,%2,%3}, {%4,%5,%6,%7}, {%8,%9}, {%0,%1,%2,%3};"
        : "+f"(c[0]), "+f"(c[1]), "+f"(c[2]), "+f"(c[3])
        : "r"(a[0]), "r"(a[1]), "r"(a[2]), "r"(a[3]), "r"(b0), "r"(b1));
}

__global__ __launch_bounds__(256) void gemm_bf16x3_kernel(
    const float* __restrict__ A, const float* __restrict__ B,
    const float* __restrict__ bias, float* __restrict__ C,
    int M, int N, int K)
{
    __shared__ __nv_bfloat16 Ah[BM * ASTR];
    __shared__ __nv_bfloat16 Al[BM * ASTR];
    __shared__ __nv_bfloat16 Bh[BK * BSTR];
    __shared__ __nv_bfloat16 Bl[BK * BSTR];

    int tid = threadIdx.x;
    int lane = tid & 31, wid = tid >> 5;
    int wm = wid & 3, wn = wid >> 2;          // warp tile: rows wm*32, cols wn*64
    int bm = blockIdx.y * BM, bn = blockIdx.x * BN;

    float acc[2][8][4];
#pragma unroll
    for (int i = 0; i < 2; i++)
#pragma unroll
        for (int j = 0; j < 8; j++)
#pragma unroll
            for (int l = 0; l < 4; l++) acc[i][j][l] = 0.f;

    const float* Ap = A + (size_t)bm * K;
    const float* Bp = B + bn;

    for (int k0 = 0; k0 < K; k0 += BK) {
        __syncthreads();
        // Load A tile (128 x 32 fp32), split -> bf16 hi/lo
#pragma unroll
        for (int i = 0; i < 4; i++) {
            int idx = tid + i * 256;
            int row = idx >> 3, c4 = idx & 7;             // 8 float4 per row
            float4 v = *(const float4*)(Ap + (size_t)row * K + k0 + c4 * 4);
            uint32_t h0, l0, h1, l1;
            split2(v.x, v.y, h0, l0);
            split2(v.z, v.w, h1, l1);
            uint32_t* dh = (uint32_t*)(Ah + row * ASTR + c4 * 4);
            uint32_t* dl = (uint32_t*)(Al + row * ASTR + c4 * 4);
            dh[0] = h0; dh[1] = h1;
            dl[0] = l0; dl[1] = l1;
        }
        // Load B tile (32 x 128 fp32), split
#pragma unroll
        for (int i = 0; i < 4; i++) {
            int idx = tid + i * 256;
            int row = idx >> 5, c4 = idx & 31;            // 32 float4 per row
            float4 v = *(const float4*)(Bp + (size_t)(k0 + row) * N + c4 * 4);
            uint32_t h0, l0, h1, l1;
            split2(v.x, v.y, h0, l0);
            split2(v.z, v.w, h1, l1);
            uint32_t* dh = (uint32_t*)(Bh + row * BSTR + c4 * 4);
            uint32_t* dl = (uint32_t*)(Bl + row * BSTR + c4 * 4);
            dh[0] = h0; dh[1] = h1;
            dl[0] = l0; dl[1] = l1;
        }
        __syncthreads();

#pragma unroll
        for (int s = 0; s < 2; s++) {                     // two k16 steps
            uint32_t ah[2][4], al[2][4];
#pragma unroll
            for (int mt = 0; mt < 2; mt++) {
                int r = wm * 32 + mt * 16 + (lane & 15);
                int kc = s * 16 + ((lane >> 4) << 3);
                ldm_x4(ah[mt], Ah + r * ASTR + kc);
                ldm_x4(al[mt], Al + r * ASTR + kc);
            }
#pragma unroll
            for (int nt = 0; nt < 4; nt++) {              // each covers two n8 tiles
                uint32_t bh[4], bl[4];
                int kr = s * 16 + (lane & 15);
                int nc = wn * 64 + nt * 16 + ((lane >> 4) << 3);
                ldm_x4_t(bh, Bh + kr * BSTR + nc);
                ldm_x4_t(bl, Bl + kr * BSTR + nc);
#pragma unroll
                for (int mt = 0; mt < 2; mt++) {
                    float* c0 = acc[mt][2 * nt];
                    float* c1 = acc[mt][2 * nt + 1];
                    mma_bf16(c0, ah[mt], bh[0], bh[1]);   // hi*hi
                    mma_bf16(c0, ah[mt], bl[0], bl[1]);   // hi*lo
                    mma_bf16(c0, al[mt], bh[0], bh[1]);   // lo*hi
                    mma_bf16(c1, ah[mt], bh[2], bh[3]);
                    mma_bf16(c1, ah[mt], bl[2], bl[3]);
                    mma_bf16(c1, al[mt], bh[2], bh[3]);
                }
            }
        }
    }

    // Epilogue: fragment c0,c1 -> (row, col..col+1); c2,c3 -> (row+8, ...)
#pragma unroll
    for (int mt = 0; mt < 2; mt++) {
#pragma unroll
        for (int n8 = 0; n8 < 8; n8++) {
            int row = bm + wm * 32 + mt * 16 + (lane >> 2);
            int col = bn + wn * 64 + n8 * 8 + (lane & 3) * 2;
            float b0 = bias[col], b1 = bias[col + 1];
            float2 v0 = make_float2(acc[mt][n8][0] + b0, acc[mt][n8][1] + b1);
            float2 v1 = make_float2(acc[mt][n8][2] + b0, acc[mt][n8][3] + b1);
            *(float2*)(C + (size_t)row * N + col) = v0;
            *(float2*)(C + (size_t)(row + 8) * N + col) = v1;
        }
    }
}

// ---------------------------------------------------------------------------
// Flash attention (causal), fp32 (unchanged from R1).
// ---------------------------------------------------------------------------
#define TQ 64
#define TK 64
#define QK_STR 132
#define P_STR  68

#define ATTN_SMEM_FLOATS (3 * TQ * QK_STR + TQ * P_STR + 3 * TQ)
#define ATTN_SMEM_BYTES  (ATTN_SMEM_FLOATS * 4)

__global__ __launch_bounds__(256) void attn_kernel()
{
    extern __shared__ float sm[];
    float* Qs   = sm;
    float* Ks   = Qs + TQ * QK_STR;
    float* Vs   = Ks + TK * QK_STR;
    float* Ps   = Vs + TK * QK_STR;
    float* m_sm = Ps + TQ * P_STR;
    float* l_sm = m_sm + TQ;
    float* a_sm = l_sm + TQ;

    int tid = threadIdx.x;
    int tx = tid & 15, ty = tid >> 4;
    int qt = blockIdx.x, h = blockIdx.y, b = blockIdx.z;
    int q0 = qt * TQ;

    const float* base  = g_qkv + (size_t)b * S_LEN * (3 * DMODEL);
    const float* qbase = base + h * DHEAD;
    const float* kbase = base + DMODEL + h * DHEAD;
    const float* vbase = base + 2 * DMODEL + h * DHEAD;

    for (int idx = tid; idx < TQ * (DHEAD / 4); idx += 256) {
        int r = idx >> 5;
        int c = (idx & 31) * 4;
        float4 v = *(const float4*)(qbase + (size_t)(q0 + r) * (3 * DMODEL) + c);
        float* dst = Qs + r * QK_STR + c;
        dst[0] = v.x; dst[1] = v.y; dst[2] = v.z; dst[3] = v.w;
    }
    if (tid < TQ) { m_sm[tid] = -1e30f; l_sm[tid] = 0.f; }

    float o[4][8];
#pragma unroll
    for (int i = 0; i < 4; i++)
#pragma unroll
        for (int j = 0; j < 8; j++) o[i][j] = 0.f;

    const float scale = 0.08838834764831845f;

    for (int kt = 0; kt <= qt; kt++) {
        __syncthreads();

        for (int idx = tid; idx < TK * (DHEAD / 4); idx += 256) {
            int r = idx >> 5;
            int c = (idx & 31) * 4;
            size_t g = (size_t)(kt * TK + r) * (3 * DMODEL) + c;
            float4 kv = *(const float4*)(kbase + g);
            float4 vv = *(const float4*)(vbase + g);
            float* kd = Ks + r * QK_STR + c;
            kd[0] = kv.x; kd[1] = kv.y; kd[2] = kv.z; kd[3] = kv.w;
            float* vd = Vs + r * QK_STR + c;
            vd[0] = vv.x; vd[1] = vv.y; vd[2] = vv.z; vd[3] = vv.w;
        }
        __syncthreads();

        float s[4][4];
#pragma unroll
        for (int i = 0; i < 4; i++)
#pragma unroll
            for (int j = 0; j < 4; j++) s[i][j] = 0.f;

        for (int d = 0; d < DHEAD; d++) {
            float a[4], bb[4];
#pragma unroll
            for (int i = 0; i < 4; i++) a[i] = Qs[(ty * 4 + i) * QK_STR + d];
#pragma unroll
            for (int j = 0; j < 4; j++) bb[j] = Ks[(tx * 4 + j) * QK_STR + d];
#pragma unroll
            for (int i = 0; i < 4; i++)
#pragma unroll
                for (int j = 0; j < 4; j++) s[i][j] += a[i] * bb[j];
        }

#pragma unroll
        for (int i = 0; i < 4; i++) {
            int qg = q0 + ty * 4 + i;
#pragma unroll
            for (int j = 0; j < 4; j++) {
                int kg = kt * TK + tx * 4 + j;
                s[i][j] = (kg <= qg) ? s[i][j] * scale : -1e30f;
            }
        }

        float rmax[4];
#pragma unroll
        for (int i = 0; i < 4; i++) {
            float v = fmaxf(fmaxf(s[i][0], s[i][1]), fmaxf(s[i][2], s[i][3]));
#pragma unroll
            for (int off = 1; off < 16; off <<= 1)
                v = fmaxf(v, __shfl_xor_sync(0xffffffffu, v, off));
            rmax[i] = v;
        }
        if (tx == 0) {
#pragma unroll
            for (int i = 0; i < 4; i++) {
                int r = ty * 4 + i;
                float mo = m_sm[r];
                float mn = fmaxf(mo, rmax[i]);
                a_sm[r] = __expf(mo - mn);
                m_sm[r] = mn;
            }
        }
        __syncthreads();

        float rs[4];
#pragma unroll
        for (int i = 0; i < 4; i++) {
            int r = ty * 4 + i;
            float mn = m_sm[r];
            float su = 0.f;
#pragma unroll
            for (int j = 0; j < 4; j++) {
                float p = __expf(s[i][j] - mn);
                Ps[r * P_STR + tx * 4 + j] = p;
                su += p;
            }
            rs[i] = su;
        }
#pragma unroll
        for (int i = 0; i < 4; i++)
#pragma unroll
            for (int off = 1; off < 16; off <<= 1)
                rs[i] += __shfl_xor_sync(0xffffffffu, rs[i], off);
        if (tx == 0) {
#pragma unroll
            for (int i = 0; i < 4; i++) {
                int r = ty * 4 + i;
                l_sm[r] = l_sm[r] * a_sm[r] + rs[i];
            }
        }

#pragma unroll
        for (int i = 0; i < 4; i++) {
            float al = a_sm[ty * 4 + i];
#pragma unroll
            for (int j = 0; j < 8; j++) o[i][j] *= al;
        }
        __syncthreads();

        for (int kk = 0; kk < TK; kk++) {
            float a[4], v[8];
#pragma unroll
            for (int i = 0; i < 4; i++) a[i] = Ps[(ty * 4 + i) * P_STR + kk];
#pragma unroll
            for (int j = 0; j < 8; j++) v[j] = Vs[kk * QK_STR + tx * 8 + j];
#pragma unroll
            for (int i = 0; i < 4; i++)
#pragma unroll
                for (int j = 0; j < 8; j++) o[i][j] += a[i] * v[j];
        }
    }

    __syncthreads();
#pragma unroll
    for (int i = 0; i < 4; i++) {
        int r = ty * 4 + i;
        float inv = 1.0f / l_sm[r];
        float* op = g_att + ((size_t)b * S_LEN + q0 + r) * DMODEL + h * DHEAD + tx * 8;
#pragma unroll
        for (int j = 0; j < 8; j++) op[j] = o[i][j] * inv;
    }
}

// ---------------------------------------------------------------------------
extern "C" void kernel_launch(void* const* d_in, const int* in_sizes, int n_in,
                              void* d_out, int out_size)
{
    const float* x     = (const float*)d_in[0];
    const float* W_qkv = (const float*)d_in[1];
    const float* b_qkv = (const float*)d_in[2];
    const float* W_out = (const float*)d_in[3];
    const float* b_out = (const float*)d_in[4];
    float* out = (float*)d_out;

    float *qkv = nullptr, *att = nullptr;
    cudaGetSymbolAddress((void**)&qkv, g_qkv);
    cudaGetSymbolAddress((void**)&att, g_att);

    cudaFuncSetAttribute(attn_kernel,
                         cudaFuncAttributeMaxDynamicSharedMemorySize,
                         ATTN_SMEM_BYTES);

    // 1) qkv = x @ W_qkv + b_qkv     [4096 x 6144], K=2048
    gemm_bf16x3_kernel<<<dim3(3 * DMODEL / BN, MTOT / BM), 256>>>(
        x, W_qkv, b_qkv, qkv, MTOT, 3 * DMODEL, DMODEL);

    // 2) causal flash attention -> g_att
    attn_kernel<<<dim3(S_LEN / TQ, NHEADS, BATCH), 256, ATTN_SMEM_BYTES>>>();

    // 3) out = att @ W_out + b_out   [4096 x 2048], K=2048
    gemm_bf16x3_kernel<<<dim3(DMODEL / BN, MTOT / BM), 256>>>(
        att, W_out, b_out, out, MTOT, DMODEL, DMODEL);
}

// round 3
// speedup vs baseline: 4.2119x; 2.8129x over previous
#include <cuda_runtime.h>
#include <cuda_bf16.h>
#include <cstdint>

#define S_LEN   2048
#define DMODEL  2048
#define NHEADS  16
#define DHEAD   128
#define BATCH   2
#define MTOT    (BATCH * S_LEN)

__device__ float g_qkv[BATCH * S_LEN * 3 * DMODEL];
__device__ float g_att[BATCH * S_LEN * DMODEL];

// ---------------------------------------------------------------------------
// Common tensor-core helpers (bf16 m16n8k16, fp32 accum)
// ---------------------------------------------------------------------------
__device__ __forceinline__ void split2(float a, float b, uint32_t& hi, uint32_t& lo) {
    __nv_bfloat162 h = __floats2bfloat162_rn(a, b);
    float la = a - __bfloat162float(h.x);
    float lb = b - __bfloat162float(h.y);
    __nv_bfloat162 l = __floats2bfloat162_rn(la, lb);
    hi = *reinterpret_cast<uint32_t*>(&h);
    lo = *reinterpret_cast<uint32_t*>(&l);
}
__device__ __forceinline__ void ldm_x4(uint32_t* r, const void* p) {
    uint32_t a = (uint32_t)__cvta_generic_to_shared(p);
    asm volatile("ldmatrix.sync.aligned.m8n8.x4.shared.b16 {%0,%1,%2,%3}, [%4];"
                 : "=r"(r[0]), "=r"(r[1]), "=r"(r[2]), "=r"(r[3]) : "r"(a));
}
__device__ __forceinline__ void ldm_x4_t(uint32_t* r, const void* p) {
    uint32_t a = (uint32_t)__cvta_generic_to_shared(p);
    asm volatile("ldmatrix.sync.aligned.m8n8.x4.trans.shared.b16 {%0,%1,%2,%3}, [%4];"
                 : "=r"(r[0]), "=r"(r[1]), "=r"(r[2]), "=r"(r[3]) : "r"(a));
}
__device__ __forceinline__ void mma_bf16(float* c, const uint32_t* a, uint32_t b0, uint32_t b1) {
    asm volatile(
        "mma.sync.aligned.m16n8k16.row.col.f32.bf16.bf16.f32 "
        "{%0,%1,%2,%3}, {%4,%5,%6,%7}, {%8,%9}, {%0,%1,%2,%3};"
        : "+f"(c[0]), "+f"(c[1]), "+f"(c[2]), "+f"(c[3])
        : "r"(a[0]), "r"(a[1]), "r"(a[2]), "r"(a[3]), "r"(b0), "r"(b1));
}

// ===========================================================================
// bf16x3 GEMM (unchanged from R2): C = A@B + bias
// ===========================================================================
#define BM 128
#define BN 128
#define BK 32
#define ASTR 40
#define BSTR 136

__global__ __launch_bounds__(256) void gemm_bf16x3_kernel(
    const float* __restrict__ A, const float* __restrict__ B,
    const float* __restrict__ bias, float* __restrict__ C,
    int M, int N, int K)
{
    __shared__ __nv_bfloat16 Ah[BM * ASTR];
    __shared__ __nv_bfloat16 Al[BM * ASTR];
    __shared__ __nv_bfloat16 Bh[BK * BSTR];
    __shared__ __nv_bfloat16 Bl[BK * BSTR];

    int tid = threadIdx.x;
    int lane = tid & 31, wid = tid >> 5;
    int wm = wid & 3, wn = wid >> 2;
    int bm = blockIdx.y * BM, bn = blockIdx.x * BN;

    float acc[2][8][4];
#pragma unroll
    for (int i = 0; i < 2; i++)
#pragma unroll
        for (int j = 0; j < 8; j++)
#pragma unroll
            for (int l = 0; l < 4; l++) acc[i][j][l] = 0.f;

    const float* Ap = A + (size_t)bm * K;
    const float* Bp = B + bn;

    for (int k0 = 0; k0 < K; k0 += BK) {
        __syncthreads();
#pragma unroll
        for (int i = 0; i < 4; i++) {
            int idx = tid + i * 256;
            int row = idx >> 3, c4 = idx & 7;
            float4 v = *(const float4*)(Ap + (size_t)row * K + k0 + c4 * 4);
            uint32_t h0, l0, h1, l1;
            split2(v.x, v.y, h0, l0);
            split2(v.z, v.w, h1, l1);
            uint32_t* dh = (uint32_t*)(Ah + row * ASTR + c4 * 4);
            uint32_t* dl = (uint32_t*)(Al + row * ASTR + c4 * 4);
            dh[0] = h0; dh[1] = h1;
            dl[0] = l0; dl[1] = l1;
        }
#pragma unroll
        for (int i = 0; i < 4; i++) {
            int idx = tid + i * 256;
            int row = idx >> 5, c4 = idx & 31;
            float4 v = *(const float4*)(Bp + (size_t)(k0 + row) * N + c4 * 4);
            uint32_t h0, l0, h1, l1;
            split2(v.x, v.y, h0, l0);
            split2(v.z, v.w, h1, l1);
            uint32_t* dh = (uint32_t*)(Bh + row * BSTR + c4 * 4);
            uint32_t* dl = (uint32_t*)(Bl + row * BSTR + c4 * 4);
            dh[0] = h0; dh[1] = h1;
            dl[0] = l0; dl[1] = l1;
        }
        __syncthreads();

#pragma unroll
        for (int s = 0; s < 2; s++) {
            uint32_t ah[2][4], al[2][4];
#pragma unroll
            for (int mt = 0; mt < 2; mt++) {
                int r = wm * 32 + mt * 16 + (lane & 15);
                int kc = s * 16 + ((lane >> 4) << 3);
                ldm_x4(ah[mt], Ah + r * ASTR + kc);
                ldm_x4(al[mt], Al + r * ASTR + kc);
            }
#pragma unroll
            for (int nt = 0; nt < 4; nt++) {
                uint32_t bh[4], bl[4];
                int kr = s * 16 + (lane & 15);
                int nc = wn * 64 + nt * 16 + ((lane >> 4) << 3);
                ldm_x4_t(bh, Bh + kr * BSTR + nc);
                ldm_x4_t(bl, Bl + kr * BSTR + nc);
#pragma unroll
                for (int mt = 0; mt < 2; mt++) {
                    float* c0 = acc[mt][2 * nt];
                    float* c1 = acc[mt][2 * nt + 1];
                    mma_bf16(c0, ah[mt], bh[0], bh[1]);
                    mma_bf16(c0, ah[mt], bl[0], bl[1]);
                    mma_bf16(c0, al[mt], bh[0], bh[1]);
                    mma_bf16(c1, ah[mt], bh[2], bh[3]);
                    mma_bf16(c1, ah[mt], bl[2], bl[3]);
                    mma_bf16(c1, al[mt], bh[2], bh[3]);
                }
            }
        }
    }

#pragma unroll
    for (int mt = 0; mt < 2; mt++) {
#pragma unroll
        for (int n8 = 0; n8 < 8; n8++) {
            int row = bm + wm * 32 + mt * 16 + (lane >> 2);
            int col = bn + wn * 64 + n8 * 8 + (lane & 3) * 2;
            float b0 = bias[col], b1 = bias[col + 1];
            float2 v0 = make_float2(acc[mt][n8][0] + b0, acc[mt][n8][1] + b1);
            float2 v1 = make_float2(acc[mt][n8][2] + b0, acc[mt][n8][3] + b1);
            *(float2*)(C + (size_t)row * N + col) = v0;
            *(float2*)(C + (size_t)(row + 8) * N + col) = v1;
        }
    }
}

// ===========================================================================
// Tensor-core causal flash attention, bf16x3 for QK^T and PV.
// Block: 128 threads (4 warps). TQ=64 (16 rows/warp), TK=64, D=128.
// Softmax fp32 in registers (quad shuffles). P never touches smem.
// ===========================================================================
#define TQ 64
#define TK 64
#define QSTR 136   // bf16 stride: 272B = odd multiple of 16B -> conflict-free ldmatrix

#define ATTN_SMEM_BYTES (6 * TQ * QSTR * 2)   // Qh,Ql,Kh,Kl,Vh,Vl = 104448 B

__global__ __launch_bounds__(128) void attn_tc_kernel()
{
    extern __shared__ __nv_bfloat16 smb[];
    __nv_bfloat16* Qh = smb;
    __nv_bfloat16* Ql = Qh + TQ * QSTR;
    __nv_bfloat16* Kh = Ql + TQ * QSTR;
    __nv_bfloat16* Kl = Kh + TQ * QSTR;
    __nv_bfloat16* Vh = Kl + TQ * QSTR;
    __nv_bfloat16* Vl = Vh + TQ * QSTR;

    int tid = threadIdx.x;
    int lane = tid & 31, w = tid >> 5;
    int qt = (gridDim.x - 1) - blockIdx.x;     // heavy blocks first
    int h = blockIdx.y, b = blockIdx.z;
    int q0 = qt * TQ;

    const float* base  = g_qkv + (size_t)b * S_LEN * (3 * DMODEL);
    const float* qbase = base + h * DHEAD;
    const float* kbase = base + DMODEL + h * DHEAD;
    const float* vbase = base + 2 * DMODEL + h * DHEAD;

    const float scale = 0.08838834764831845f;  // 1/sqrt(128)

    // Load + scale + split Q tile (64 x 128)
#pragma unroll
    for (int i = 0; i < 16; i++) {
        int idx = tid + i * 128;
        int r = idx >> 5, c4 = idx & 31;
        float4 v = *(const float4*)(qbase + (size_t)(q0 + r) * (3 * DMODEL) + c4 * 4);
        v.x *= scale; v.y *= scale; v.z *= scale; v.w *= scale;
        uint32_t h0, l0, h1, l1;
        split2(v.x, v.y, h0, l0);
        split2(v.z, v.w, h1, l1);
        uint32_t* dh = (uint32_t*)(Qh + r * QSTR + c4 * 4);
        uint32_t* dl = (uint32_t*)(Ql + r * QSTR + c4 * 4);
        dh[0] = h0; dh[1] = h1;
        dl[0] = l0; dl[1] = l1;
    }

    float o[16][4];
#pragma unroll
    for (int t = 0; t < 16; t++)
#pragma unroll
        for (int j = 0; j < 4; j++) o[t][j] = 0.f;
    float m0 = -1e30f, m1 = -1e30f, l0 = 0.f, l1 = 0.f;

    int qrow_lo = w * 16 + (lane >> 2);        // local q row of c0/c1
    int qrow_hi = qrow_lo + 8;                 // local q row of c2/c3

    for (int kt = 0; kt <= qt; kt++) {
        __syncthreads();
        // Load + split K,V tiles (64 x 128 each)
#pragma unroll
        for (int i = 0; i < 16; i++) {
            int idx = tid + i * 128;
            int r = idx >> 5, c4 = idx & 31;
            size_t g = (size_t)(kt * TK + r) * (3 * DMODEL) + c4 * 4;
            float4 kv = *(const float4*)(kbase + g);
            float4 vv = *(const float4*)(vbase + g);
            uint32_t h0, lo0, h1, lo1;
            split2(kv.x, kv.y, h0, lo0);
            split2(kv.z, kv.w, h1, lo1);
            uint32_t* dh = (uint32_t*)(Kh + r * QSTR + c4 * 4);
            uint32_t* dl = (uint32_t*)(Kl + r * QSTR + c4 * 4);
            dh[0] = h0; dh[1] = h1; dl[0] = lo0; dl[1] = lo1;
            split2(vv.x, vv.y, h0, lo0);
            split2(vv.z, vv.w, h1, lo1);
            dh = (uint32_t*)(Vh + r * QSTR + c4 * 4);
            dl = (uint32_t*)(Vl + r * QSTR + c4 * 4);
            dh[0] = h0; dh[1] = h1; dl[0] = lo0; dl[1] = lo1;
        }
        __syncthreads();

        // ---- S = Q K^T  (warp: 16 x 64, 8 n8-tiles) ----
        float s[8][4];
#pragma unroll
        for (int t = 0; t < 8; t++)
#pragma unroll
            for (int j = 0; j < 4; j++) s[t][j] = 0.f;

#pragma unroll
        for (int ks = 0; ks < 8; ks++) {
            uint32_t ah[4], al[4];
            const int arow = (w * 16 + (lane & 15)) * QSTR + ks * 16 + ((lane >> 4) << 3);
            ldm_x4(ah, Qh + arow);
            ldm_x4(al, Ql + arow);
#pragma unroll
            for (int nt2 = 0; nt2 < 4; nt2++) {
                uint32_t kh[4], kl[4];
                const int krow = (nt2 * 16 + (lane & 15)) * QSTR + ks * 16 + ((lane >> 4) << 3);
                ldm_x4(kh, Kh + krow);   // non-trans: K rows are the n dim
                ldm_x4(kl, Kl + krow);
                float* c0 = s[2 * nt2];
                float* c1 = s[2 * nt2 + 1];
                mma_bf16(c0, ah, kh[0], kh[2]);
                mma_bf16(c0, ah, kl[0], kl[2]);
                mma_bf16(c0, al, kh[0], kh[2]);
                mma_bf16(c1, ah, kh[1], kh[3]);
                mma_bf16(c1, ah, kl[1], kl[3]);
                mma_bf16(c1, al, kh[1], kh[3]);
            }
        }

        // ---- causal mask (only on the diagonal tile) ----
        if (kt == qt) {
#pragma unroll
            for (int t = 0; t < 8; t++) {
                int col = t * 8 + (lane & 3) * 2;
                if (col > qrow_lo)     s[t][0] = -1e30f;
                if (col + 1 > qrow_lo) s[t][1] = -1e30f;
                if (col > qrow_hi)     s[t][2] = -1e30f;
                if (col + 1 > qrow_hi) s[t][3] = -1e30f;
            }
        }

        // ---- online softmax (fp32, quad shuffles) ----
        float mx0 = -1e30f, mx1 = -1e30f;
#pragma unroll
        for (int t = 0; t < 8; t++) {
            mx0 = fmaxf(mx0, fmaxf(s[t][0], s[t][1]));
            mx1 = fmaxf(mx1, fmaxf(s[t][2], s[t][3]));
        }
        mx0 = fmaxf(mx0, __shfl_xor_sync(0xffffffffu, mx0, 1));
        mx0 = fmaxf(mx0, __shfl_xor_sync(0xffffffffu, mx0, 2));
        mx1 = fmaxf(mx1, __shfl_xor_sync(0xffffffffu, mx1, 1));
        mx1 = fmaxf(mx1, __shfl_xor_sync(0xffffffffu, mx1, 2));

        float mn0 = fmaxf(m0, mx0), mn1 = fmaxf(m1, mx1);
        float al0 = __expf(m0 - mn0), al1 = __expf(m1 - mn1);
        m0 = mn0; m1 = mn1;

        float rs0 = 0.f, rs1 = 0.f;
#pragma unroll
        for (int t = 0; t < 8; t++) {
            s[t][0] = __expf(s[t][0] - mn0);
            s[t][1] = __expf(s[t][1] - mn0);
            s[t][2] = __expf(s[t][2] - mn1);
            s[t][3] = __expf(s[t][3] - mn1);
            rs0 += s[t][0] + s[t][1];
            rs1 += s[t][2] + s[t][3];
        }
        rs0 += __shfl_xor_sync(0xffffffffu, rs0, 1);
        rs0 += __shfl_xor_sync(0xffffffffu, rs0, 2);
        rs1 += __shfl_xor_sync(0xffffffffu, rs1, 1);
        rs1 += __shfl_xor_sync(0xffffffffu, rs1, 2);
        l0 = l0 * al0 + rs0;
        l1 = l1 * al1 + rs1;

        // rescale running O
#pragma unroll
        for (int t = 0; t < 16; t++) {
            o[t][0] *= al0; o[t][1] *= al0;
            o[t][2] *= al1; o[t][3] *= al1;
        }

        // ---- split P into bf16 hi/lo A-fragments (register-only) ----
        uint32_t pah[4][4], pal[4][4];   // [k16 step][frag reg]
#pragma unroll
        for (int ks = 0; ks < 4; ks++) {
            int t0 = 2 * ks, t1 = 2 * ks + 1;
            split2(s[t0][0], s[t0][1], pah[ks][0], pal[ks][0]);
            split2(s[t0][2], s[t0][3], pah[ks][1], pal[ks][1]);
            split2(s[t1][0], s[t1][1], pah[ks][2], pal[ks][2]);
            split2(s[t1][2], s[t1][3], pah[ks][3], pal[ks][3]);
        }

        // ---- O += P @ V  (warp: 16 x 128, 16 n8-tiles, 4 k16 steps) ----
#pragma unroll
        for (int ks = 0; ks < 4; ks++) {
#pragma unroll
            for (int nt2 = 0; nt2 < 8; nt2++) {
                uint32_t bh[4], bl[4];
                const int vrow = (ks * 16 + (lane & 15)) * QSTR + nt2 * 16 + ((lane >> 4) << 3);
                ldm_x4_t(bh, Vh + vrow);
                ldm_x4_t(bl, Vl + vrow);
                float* c0 = o[2 * nt2];
                float* c1 = o[2 * nt2 + 1];
                mma_bf16(c0, pah[ks], bh[0], bh[1]);
                mma_bf16(c0, pah[ks], bl[0], bl[1]);
                mma_bf16(c0, pal[ks], bh[0], bh[1]);
                mma_bf16(c1, pah[ks], bh[2], bh[3]);
                mma_bf16(c1, pah[ks], bl[2], bl[3]);
                mma_bf16(c1, pal[ks], bh[2], bh[3]);
            }
        }
    }

    // ---- write O / l ----
    float inv0 = 1.0f / l0, inv1 = 1.0f / l1;
    int row0 = q0 + qrow_lo;
    int row1 = q0 + qrow_hi;
#pragma unroll
    for (int t = 0; t < 16; t++) {
        int col = t * 8 + (lane & 3) * 2;
        float* p0 = g_att + ((size_t)b * S_LEN + row0) * DMODEL + h * DHEAD + col;
        float* p1 = g_att + ((size_t)b * S_LEN + row1) * DMODEL + h * DHEAD + col;
        *(float2*)p0 = make_float2(o[t][0] * inv0, o[t][1] * inv0);
        *(float2*)p1 = make_float2(o[t][2] * inv1, o[t][3] * inv1);
    }
}

// ---------------------------------------------------------------------------
extern "C" void kernel_launch(void* const* d_in, const int* in_sizes, int n_in,
                              void* d_out, int out_size)
{
    const float* x     = (const float*)d_in[0];
    const float* W_qkv = (const float*)d_in[1];
    const float* b_qkv = (const float*)d_in[2];
    const float* W_out = (const float*)d_in[3];
    const float* b_out = (const float*)d_in[4];
    float* out = (float*)d_out;

    float *qkv = nullptr, *att = nullptr;
    cudaGetSymbolAddress((void**)&qkv, g_qkv);
    cudaGetSymbolAddress((void**)&att, g_att);

    cudaFuncSetAttribute(attn_tc_kernel,
                         cudaFuncAttributeMaxDynamicSharedMemorySize,
                         ATTN_SMEM_BYTES);

    gemm_bf16x3_kernel<<<dim3(3 * DMODEL / BN, MTOT / BM), 256>>>(
        x, W_qkv, b_qkv, qkv, MTOT, 3 * DMODEL, DMODEL);

    attn_tc_kernel<<<dim3(S_LEN / TQ, NHEADS, BATCH), 128, ATTN_SMEM_BYTES>>>();

    gemm_bf16x3_kernel<<<dim3(DMODEL / BN, MTOT / BM), 256>>>(
        att, W_out, b_out, out, MTOT, DMODEL, DMODEL);
}